// round 13
// baseline (speedup 1.0000x reference)
#include <cuda_runtime.h>
#include <cuda_fp16.h>

#define NV 4096            // nodes per graph
#define NB 32              // batch size (== warp size, load-bearing)
#define BN (NV * NB)       // 131072
#define CAP 256            // ELL row capacity (mean degree 128, +11 sigma headroom)
#define CSTRIDE 32         // counter padding: 1 counter per 128B line

// ---- scratch (device globals; counters zero at entry: BSS on first call,
//      self-zeroed by k_mu/k_dx on every call) ----
__device__ float  g_xt   [BN];           // x,  node-major [node][batch] (fp32)
__device__ float  g_fxt  [BN];           // tanh(x), node-major (fp32, epilogue)
__device__ __half g_fxt16[BN];           // tanh(x), node-major (fp16, gathers)
__device__ float  g_epst [BN];           // eps, node-major (fp32, epilogue)
__device__ __half g_epst16[BN];          // eps, node-major (fp16, gathers)
__device__ int    g_cnt_dst[NV * CSTRIDE];   // padded: index node*32
__device__ int    g_cnt_src[NV * CSTRIDE];
__device__ float2 g_ellF[NV * CAP];      // rows keyed by dst: (src*32, w)
__device__ float2 g_ellB[NV * CAP];      // rows keyed by src: (dst*32, w)

// ============================================================================
// Fused build + prep. 256 threads/block.
// blocks [0, nb)      : ELL build, 4 edges/thread (R6-proven shape)
// blocks [nb, nb+128) : transpose x [B,N] -> node-major + tanh (fp32 + fp16)
// Build blocks come first so the long pole starts immediately; prep overlaps.
// ============================================================================
__global__ void __launch_bounds__(256) k_pb(const float* __restrict__ x,
                                            const float* __restrict__ w,
                                            const int*   __restrict__ esrc,
                                            const int*   __restrict__ edst,
                                            int E, int nb) {
    if (blockIdx.x >= (unsigned)nb) {
        // ---- prep: 32x32 tile, 8 warps, 4 row-iterations ----
        __shared__ float s[32][33];
        int tx  = threadIdx.x & 31;
        int ty0 = threadIdx.x >> 5;          // 0..7
        int i0  = (blockIdx.x - nb) * 32;
        #pragma unroll
        for (int r = 0; r < 4; r++) {
            int ty = ty0 + (r << 3);
            s[ty][tx] = x[ty * NV + i0 + tx];            // batch-major read
        }
        __syncthreads();
        #pragma unroll
        for (int r = 0; r < 4; r++) {
            int ty = ty0 + (r << 3);
            float xv = s[tx][ty];
            float fx = tanhf(xv);
            int o = (i0 + ty) * NB + tx;                 // node-major write
            g_xt[o]    = xv;
            g_fxt[o]   = fx;
            g_fxt16[o] = __float2half_rn(fx);
        }
        return;
    }
    // ---- build: 4 edges/thread, padded counters, prescaled columns ----
    int t  = blockIdx.x * 256 + threadIdx.x;
    int e0 = t << 2;
    if (e0 >= E) return;
    if (e0 + 4 <= E) {
        int4   s4 = *(const int4*)  (esrc + e0);
        int4   d4 = *(const int4*)  (edst + e0);
        float4 w4 = *(const float4*)(w    + e0);
        int p0 = atomicAdd(&g_cnt_dst[d4.x << 5], 1);
        int p1 = atomicAdd(&g_cnt_dst[d4.y << 5], 1);
        int p2 = atomicAdd(&g_cnt_dst[d4.z << 5], 1);
        int p3 = atomicAdd(&g_cnt_dst[d4.w << 5], 1);
        int q0 = atomicAdd(&g_cnt_src[s4.x << 5], 1);
        int q1 = atomicAdd(&g_cnt_src[s4.y << 5], 1);
        int q2 = atomicAdd(&g_cnt_src[s4.z << 5], 1);
        int q3 = atomicAdd(&g_cnt_src[s4.w << 5], 1);
        if (p0 < CAP) g_ellF[(d4.x << 8) + p0] = make_float2(__int_as_float(s4.x << 5), w4.x);
        if (p1 < CAP) g_ellF[(d4.y << 8) + p1] = make_float2(__int_as_float(s4.y << 5), w4.y);
        if (p2 < CAP) g_ellF[(d4.z << 8) + p2] = make_float2(__int_as_float(s4.z << 5), w4.z);
        if (p3 < CAP) g_ellF[(d4.w << 8) + p3] = make_float2(__int_as_float(s4.w << 5), w4.w);
        if (q0 < CAP) g_ellB[(s4.x << 8) + q0] = make_float2(__int_as_float(d4.x << 5), w4.x);
        if (q1 < CAP) g_ellB[(s4.y << 8) + q1] = make_float2(__int_as_float(d4.y << 5), w4.y);
        if (q2 < CAP) g_ellB[(s4.z << 8) + q2] = make_float2(__int_as_float(d4.z << 5), w4.z);
        if (q3 < CAP) g_ellB[(s4.w << 8) + q3] = make_float2(__int_as_float(d4.w << 5), w4.w);
    } else {
        for (int e = e0; e < E; e++) {
            int s = esrc[e], d = edst[e];
            float wt = w[e];
            int p = atomicAdd(&g_cnt_dst[d << 5], 1);
            if (p < CAP) g_ellF[(d << 8) + p] = make_float2(__int_as_float(s << 5), wt);
            int q = atomicAdd(&g_cnt_src[s << 5], 1);
            if (q < CAP) g_ellB[(s << 8) + q] = make_float2(__int_as_float(d << 5), wt);
        }
    }
}

// SpMM inner loop over smem-staged row [jb,je): LDS.64 broadcast of
// (colOff, w), fp16 1-sector gathers via pre-offset lane pointer,
// unroll-8 for 8 gathers in flight. (R10-proven structure.)
__device__ __forceinline__ float spmm_smem(const float2* row,
                                           const __half* __restrict__ tabl,
                                           int jb, int je) {
    float a0 = 0.f, a1 = 0.f, a2 = 0.f, a3 = 0.f;
    int j = jb;
    for (; j + 8 <= je; j += 8) {
        float2 e0 = row[j + 0]; float2 e1 = row[j + 1];
        float2 e2 = row[j + 2]; float2 e3 = row[j + 3];
        float2 e4 = row[j + 4]; float2 e5 = row[j + 5];
        float2 e6 = row[j + 6]; float2 e7 = row[j + 7];
        float v0 = __half2float(tabl[__float_as_int(e0.x)]);
        float v1 = __half2float(tabl[__float_as_int(e1.x)]);
        float v2 = __half2float(tabl[__float_as_int(e2.x)]);
        float v3 = __half2float(tabl[__float_as_int(e3.x)]);
        float v4 = __half2float(tabl[__float_as_int(e4.x)]);
        float v5 = __half2float(tabl[__float_as_int(e5.x)]);
        float v6 = __half2float(tabl[__float_as_int(e6.x)]);
        float v7 = __half2float(tabl[__float_as_int(e7.x)]);
        a0 = fmaf(e0.y, v0, a0); a1 = fmaf(e1.y, v1, a1);
        a2 = fmaf(e2.y, v2, a2); a3 = fmaf(e3.y, v3, a3);
        a0 = fmaf(e4.y, v4, a0); a1 = fmaf(e5.y, v5, a1);
        a2 = fmaf(e6.y, v6, a2); a3 = fmaf(e7.y, v7, a3);
    }
    for (; j < je; j++) {
        float2 e0 = row[j];
        a0 = fmaf(e0.y, __half2float(tabl[__float_as_int(e0.x)]), a0);
    }
    return (a0 + a1) + (a2 + a3);
}

// Forward SpMM: mu = sum w * fx[src]; eps = x - mu (fp32 + fp16);
// mu written straight to out[0] batch-major (scattered 4B stores).
__global__ void __launch_bounds__(256, 8) k_mu(float* __restrict__ out) {
    __shared__ float2 srow[2][CAP];
    __shared__ float  part[2][4][32];
    int warp  = threadIdx.x >> 5;
    int lane  = threadIdx.x & 31;
    int local = warp >> 2;
    int q     = warp & 3;
    int node0 = blockIdx.x << 1;

    int n0 = min(g_cnt_dst[node0 << 5],       CAP);
    int n1 = min(g_cnt_dst[(node0 + 1) << 5], CAP);
    for (int i = threadIdx.x; i < n0; i += 256) srow[0][i] = g_ellF[(node0 << 8) + i];
    for (int i = threadIdx.x; i < n1; i += 256) srow[1][i] = g_ellF[((node0 + 1) << 8) + i];
    __syncthreads();

    int n  = local ? n1 : n0;
    int jb = (n * q) >> 2;
    int je = (n * (q + 1)) >> 2;
    const __half* tabl = g_fxt16 + lane;

    part[local][q][lane] = spmm_smem(srow[local], tabl, jb, je);
    __syncthreads();

    if (q == 0) {
        float mu = (part[local][0][lane] + part[local][1][lane])
                 + (part[local][2][lane] + part[local][3][lane]);
        int node = node0 + local;
        int o = (node << 5) + lane;
        float eps = g_xt[o] - mu;
        g_epst[o]   = eps;
        g_epst16[o] = __float2half_rn(eps);
        out[lane * NV + node] = mu;                     // batch-major, scattered
        if (lane == 0) g_cnt_dst[node << 5] = 0;        // restore invariant
    }
}

// Backward SpMM: dx = -eps + (1-fx^2) * sum w * eps[dst];
// dx written straight to out[1] batch-major.
__global__ void __launch_bounds__(256, 8) k_dx(float* __restrict__ out) {
    __shared__ float2 srow[2][CAP];
    __shared__ float  part[2][4][32];
    int warp  = threadIdx.x >> 5;
    int lane  = threadIdx.x & 31;
    int local = warp >> 2;
    int q     = warp & 3;
    int node0 = blockIdx.x << 1;

    int n0 = min(g_cnt_src[node0 << 5],       CAP);
    int n1 = min(g_cnt_src[(node0 + 1) << 5], CAP);
    for (int i = threadIdx.x; i < n0; i += 256) srow[0][i] = g_ellB[(node0 << 8) + i];
    for (int i = threadIdx.x; i < n1; i += 256) srow[1][i] = g_ellB[((node0 + 1) << 8) + i];
    __syncthreads();

    int n  = local ? n1 : n0;
    int jb = (n * q) >> 2;
    int je = (n * (q + 1)) >> 2;
    const __half* tabl = g_epst16 + lane;

    part[local][q][lane] = spmm_smem(srow[local], tabl, jb, je);
    __syncthreads();

    if (q == 0) {
        float acc = (part[local][0][lane] + part[local][1][lane])
                  + (part[local][2][lane] + part[local][3][lane]);
        int node = node0 + local;
        int o = (node << 5) + lane;
        float eps = g_epst[o];
        float fx  = g_fxt[o];
        out[BN + lane * NV + node] = fmaf(fmaf(-fx, fx, 1.0f), acc, -eps);
        if (lane == 0) g_cnt_src[node << 5] = 0;        // restore invariant
    }
}

extern "C" void kernel_launch(void* const* d_in, const int* in_sizes, int n_in,
                              void* d_out, int out_size) {
    const float* x    = (const float*)d_in[0];
    const float* w    = (const float*)d_in[1];
    const int*   esrc = (const int*)d_in[2];
    const int*   edst = (const int*)d_in[3];
    float*       out  = (float*)d_out;
    int E  = in_sizes[1];
    int nb = ((E + 3) / 4 + 255) / 256;      // build blocks

    k_pb<<<nb + 128, 256>>>(x, w, esrc, edst, E, nb);
    k_mu<<<NV / 2, 256>>>(out);
    k_dx<<<NV / 2, 256>>>(out);
}

// round 14
// speedup vs baseline: 1.0041x; 1.0041x over previous
#include <cuda_runtime.h>
#include <cuda_fp16.h>

#define NV 4096            // nodes per graph
#define NB 32              // batch size (== warp size, load-bearing)
#define BN (NV * NB)       // 131072
#define CAP 256            // ELL row capacity (mean degree 128, +11 sigma headroom)
#define CSTRIDE 32         // counter padding: 1 counter per 128B line

// ---- scratch (device globals; counters zero at entry: BSS on first call,
//      self-zeroed by k_mu/k_dx on every call) ----
__device__ float  g_xt   [BN];           // x,  node-major [node][batch] (fp32)
__device__ float  g_fxt  [BN];           // tanh(x), node-major (fp32, epilogue)
__device__ __half g_fxt16[BN];           // tanh(x), node-major (fp16, gathers)
__device__ float  g_epst [BN];           // eps, node-major (fp32, epilogue)
__device__ __half g_epst16[BN];          // eps, node-major (fp16, gathers)
__device__ int    g_cnt_dst[NV * CSTRIDE];   // padded: index node*32
__device__ int    g_cnt_src[NV * CSTRIDE];
__device__ float2 g_ellF[NV * CAP];      // rows keyed by dst: (src*32, w)
__device__ float2 g_ellB[NV * CAP];      // rows keyed by src: (dst*32, w)

// ============================================================================
// k_pf: forward-direction build + prep. 256 threads/block.
// blocks [0, nbF)      : buildF only (2 scattered L2 ops/edge), 4 edges/thread
// blocks [nbF, nbF+128): transpose x [B,N] -> node-major + tanh (fp32 + fp16)
// ============================================================================
__global__ void __launch_bounds__(256) k_pf(const float* __restrict__ x,
                                            const float* __restrict__ w,
                                            const int*   __restrict__ esrc,
                                            const int*   __restrict__ edst,
                                            int E, int nbF) {
    if (blockIdx.x >= (unsigned)nbF) {
        __shared__ float s[32][33];
        int tx  = threadIdx.x & 31;
        int ty0 = threadIdx.x >> 5;          // 0..7
        int i0  = (blockIdx.x - nbF) * 32;
        #pragma unroll
        for (int r = 0; r < 4; r++) {
            int ty = ty0 + (r << 3);
            s[ty][tx] = x[ty * NV + i0 + tx];            // batch-major read
        }
        __syncthreads();
        #pragma unroll
        for (int r = 0; r < 4; r++) {
            int ty = ty0 + (r << 3);
            float xv = s[tx][ty];
            float fx = tanhf(xv);
            int o = (i0 + ty) * NB + tx;                 // node-major write
            g_xt[o]    = xv;
            g_fxt[o]   = fx;
            g_fxt16[o] = __float2half_rn(fx);
        }
        return;
    }
    // ---- buildF: rows keyed by dst ----
    int t  = blockIdx.x * 256 + threadIdx.x;
    int e0 = t << 2;
    if (e0 >= E) return;
    if (e0 + 4 <= E) {
        int4   s4 = *(const int4*)  (esrc + e0);
        int4   d4 = *(const int4*)  (edst + e0);
        float4 w4 = *(const float4*)(w    + e0);
        int p0 = atomicAdd(&g_cnt_dst[d4.x << 5], 1);
        int p1 = atomicAdd(&g_cnt_dst[d4.y << 5], 1);
        int p2 = atomicAdd(&g_cnt_dst[d4.z << 5], 1);
        int p3 = atomicAdd(&g_cnt_dst[d4.w << 5], 1);
        if (p0 < CAP) g_ellF[(d4.x << 8) + p0] = make_float2(__int_as_float(s4.x << 5), w4.x);
        if (p1 < CAP) g_ellF[(d4.y << 8) + p1] = make_float2(__int_as_float(s4.y << 5), w4.y);
        if (p2 < CAP) g_ellF[(d4.z << 8) + p2] = make_float2(__int_as_float(s4.z << 5), w4.z);
        if (p3 < CAP) g_ellF[(d4.w << 8) + p3] = make_float2(__int_as_float(s4.w << 5), w4.w);
    } else {
        for (int e = e0; e < E; e++) {
            int s = esrc[e], d = edst[e];
            int p = atomicAdd(&g_cnt_dst[d << 5], 1);
            if (p < CAP) g_ellF[(d << 8) + p] = make_float2(__int_as_float(s << 5), w[e]);
        }
    }
}

// SpMM inner loop over smem-staged row [jb,je): LDS.64 broadcast of
// (colOff, w), fp16 1-sector gathers via pre-offset lane pointer,
// unroll-8 for 8 gathers in flight. (R10-proven structure.)
__device__ __forceinline__ float spmm_smem(const float2* row,
                                           const __half* __restrict__ tabl,
                                           int jb, int je) {
    float a0 = 0.f, a1 = 0.f, a2 = 0.f, a3 = 0.f;
    int j = jb;
    for (; j + 8 <= je; j += 8) {
        float2 e0 = row[j + 0]; float2 e1 = row[j + 1];
        float2 e2 = row[j + 2]; float2 e3 = row[j + 3];
        float2 e4 = row[j + 4]; float2 e5 = row[j + 5];
        float2 e6 = row[j + 6]; float2 e7 = row[j + 7];
        float v0 = __half2float(tabl[__float_as_int(e0.x)]);
        float v1 = __half2float(tabl[__float_as_int(e1.x)]);
        float v2 = __half2float(tabl[__float_as_int(e2.x)]);
        float v3 = __half2float(tabl[__float_as_int(e3.x)]);
        float v4 = __half2float(tabl[__float_as_int(e4.x)]);
        float v5 = __half2float(tabl[__float_as_int(e5.x)]);
        float v6 = __half2float(tabl[__float_as_int(e6.x)]);
        float v7 = __half2float(tabl[__float_as_int(e7.x)]);
        a0 = fmaf(e0.y, v0, a0); a1 = fmaf(e1.y, v1, a1);
        a2 = fmaf(e2.y, v2, a2); a3 = fmaf(e3.y, v3, a3);
        a0 = fmaf(e4.y, v4, a0); a1 = fmaf(e5.y, v5, a1);
        a2 = fmaf(e6.y, v6, a2); a3 = fmaf(e7.y, v7, a3);
    }
    for (; j < je; j++) {
        float2 e0 = row[j];
        a0 = fmaf(e0.y, __half2float(tabl[__float_as_int(e0.x)]), a0);
    }
    return (a0 + a1) + (a2 + a3);
}

// ============================================================================
// k_mu with buildB riding along: blocks [0, nbB) build the src-keyed ELL
// (consumed only by k_dx — kernel boundary orders it); blocks [nbB, ...)
// do the forward SpMM. Build blocks co-schedule with mu's latency-bound
// gather blocks and use the idle L2/issue capacity.
// ============================================================================
__global__ void __launch_bounds__(256, 8) k_mu(float* __restrict__ out,
                                               const float* __restrict__ w,
                                               const int*   __restrict__ esrc,
                                               const int*   __restrict__ edst,
                                               int E, int nbB) {
    if (blockIdx.x < (unsigned)nbB) {
        // ---- buildB: rows keyed by src ----
        int t  = blockIdx.x * 256 + threadIdx.x;
        int e0 = t << 2;
        if (e0 >= E) return;
        if (e0 + 4 <= E) {
            int4   s4 = *(const int4*)  (esrc + e0);
            int4   d4 = *(const int4*)  (edst + e0);
            float4 w4 = *(const float4*)(w    + e0);
            int q0 = atomicAdd(&g_cnt_src[s4.x << 5], 1);
            int q1 = atomicAdd(&g_cnt_src[s4.y << 5], 1);
            int q2 = atomicAdd(&g_cnt_src[s4.z << 5], 1);
            int q3 = atomicAdd(&g_cnt_src[s4.w << 5], 1);
            if (q0 < CAP) g_ellB[(s4.x << 8) + q0] = make_float2(__int_as_float(d4.x << 5), w4.x);
            if (q1 < CAP) g_ellB[(s4.y << 8) + q1] = make_float2(__int_as_float(d4.y << 5), w4.y);
            if (q2 < CAP) g_ellB[(s4.z << 8) + q2] = make_float2(__int_as_float(d4.z << 5), w4.z);
            if (q3 < CAP) g_ellB[(s4.w << 8) + q3] = make_float2(__int_as_float(d4.w << 5), w4.w);
        } else {
            for (int e = e0; e < E; e++) {
                int s = esrc[e], d = edst[e];
                int q = atomicAdd(&g_cnt_src[s << 5], 1);
                if (q < CAP) g_ellB[(s << 8) + q] = make_float2(__int_as_float(d << 5), w[e]);
            }
        }
        return;
    }
    // ---- forward SpMM: mu = sum w * fx[src]; eps = x - mu ----
    __shared__ float2 srow[2][CAP];
    __shared__ float  part[2][4][32];
    int warp  = threadIdx.x >> 5;
    int lane  = threadIdx.x & 31;
    int local = warp >> 2;
    int q     = warp & 3;
    int node0 = (blockIdx.x - nbB) << 1;

    int n0 = min(g_cnt_dst[node0 << 5],       CAP);
    int n1 = min(g_cnt_dst[(node0 + 1) << 5], CAP);
    for (int i = threadIdx.x; i < n0; i += 256) srow[0][i] = g_ellF[(node0 << 8) + i];
    for (int i = threadIdx.x; i < n1; i += 256) srow[1][i] = g_ellF[((node0 + 1) << 8) + i];
    __syncthreads();

    int n  = local ? n1 : n0;
    int jb = (n * q) >> 2;
    int je = (n * (q + 1)) >> 2;
    const __half* tabl = g_fxt16 + lane;

    part[local][q][lane] = spmm_smem(srow[local], tabl, jb, je);
    __syncthreads();

    if (q == 0) {
        float mu = (part[local][0][lane] + part[local][1][lane])
                 + (part[local][2][lane] + part[local][3][lane]);
        int node = node0 + local;
        int o = (node << 5) + lane;
        float eps = g_xt[o] - mu;
        g_epst[o]   = eps;
        g_epst16[o] = __float2half_rn(eps);
        out[lane * NV + node] = mu;                     // batch-major, scattered
        if (lane == 0) g_cnt_dst[node << 5] = 0;        // restore invariant
    }
}

// Backward SpMM: dx = -eps + (1-fx^2) * sum w * eps[dst];
// dx written straight to out[1] batch-major.
__global__ void __launch_bounds__(256, 8) k_dx(float* __restrict__ out) {
    __shared__ float2 srow[2][CAP];
    __shared__ float  part[2][4][32];
    int warp  = threadIdx.x >> 5;
    int lane  = threadIdx.x & 31;
    int local = warp >> 2;
    int q     = warp & 3;
    int node0 = blockIdx.x << 1;

    int n0 = min(g_cnt_src[node0 << 5],       CAP);
    int n1 = min(g_cnt_src[(node0 + 1) << 5], CAP);
    for (int i = threadIdx.x; i < n0; i += 256) srow[0][i] = g_ellB[(node0 << 8) + i];
    for (int i = threadIdx.x; i < n1; i += 256) srow[1][i] = g_ellB[((node0 + 1) << 8) + i];
    __syncthreads();

    int n  = local ? n1 : n0;
    int jb = (n * q) >> 2;
    int je = (n * (q + 1)) >> 2;
    const __half* tabl = g_epst16 + lane;

    part[local][q][lane] = spmm_smem(srow[local], tabl, jb, je);
    __syncthreads();

    if (q == 0) {
        float acc = (part[local][0][lane] + part[local][1][lane])
                  + (part[local][2][lane] + part[local][3][lane]);
        int node = node0 + local;
        int o = (node << 5) + lane;
        float eps = g_epst[o];
        float fx  = g_fxt[o];
        out[BN + lane * NV + node] = fmaf(fmaf(-fx, fx, 1.0f), acc, -eps);
        if (lane == 0) g_cnt_src[node << 5] = 0;        // restore invariant
    }
}

extern "C" void kernel_launch(void* const* d_in, const int* in_sizes, int n_in,
                              void* d_out, int out_size) {
    const float* x    = (const float*)d_in[0];
    const float* w    = (const float*)d_in[1];
    const int*   esrc = (const int*)d_in[2];
    const int*   edst = (const int*)d_in[3];
    float*       out  = (float*)d_out;
    int E  = in_sizes[1];
    int nb = ((E + 3) / 4 + 255) / 256;      // build blocks per direction

    k_pf<<<nb + 128, 256>>>(x, w, esrc, edst, E, nb);
    k_mu<<<nb + NV / 2, 256>>>(out, w, esrc, edst, E, nb);
    k_dx<<<NV / 2, 256>>>(out);
}

// round 15
// speedup vs baseline: 1.0547x; 1.0504x over previous
#include <cuda_runtime.h>
#include <cuda_fp16.h>

#define NV 4096            // nodes per graph
#define NB 32              // batch size (== warp size, load-bearing)
#define BN (NV * NB)       // 131072
#define CAP 256            // ELL row capacity (mean degree 128, +11 sigma headroom)
#define CSTRIDE 32         // counter padding: 1 counter per 128B line

// ---- scratch (device globals; counters zero at entry: BSS on first call,
//      self-zeroed by k_mu/k_dx on every call) ----
__device__ float  g_xt   [BN];           // x,  node-major [node][batch] (fp32)
__device__ float  g_fxt  [BN];           // tanh(x), node-major (fp32, epilogue)
__device__ __half g_fxt16[BN];           // tanh(x), node-major (fp16, gathers)
__device__ float  g_epst [BN];           // eps, node-major (fp32, epilogue)
__device__ __half g_epst16[BN];          // eps, node-major (fp16, gathers)
__device__ int    g_cnt_dst[NV * CSTRIDE];   // padded: index node*32
__device__ int    g_cnt_src[NV * CSTRIDE];
__device__ float2 g_ellF[NV * CAP];      // rows keyed by dst: (src*32, w)
__device__ float2 g_ellB[NV * CAP];      // rows keyed by src: (dst*32, w)

__device__ __forceinline__ void insF(int s, int d, float wt) {
    int p = atomicAdd(&g_cnt_dst[d << 5], 1);
    if (p < CAP) g_ellF[(d << 8) + p] = make_float2(__int_as_float(s << 5), wt);
}

// ============================================================================
// k_pf: forward build (dst-keyed) + prep. 128 threads/block.
// Build blocks [0, nbF): each thread handles TWO 4-edge segments (from the
// two halves of the edge list) -> 8 independent ATOMG chains per thread while
// the grid stays large (nbF = E/1024 = 512 blocks).
// Prep blocks [nbF, nbF+128): transpose + tanh, 4 warps x 8 row-iterations.
// ============================================================================
__global__ void __launch_bounds__(128) k_pf(const float* __restrict__ x,
                                            const float* __restrict__ w,
                                            const int*   __restrict__ esrc,
                                            const int*   __restrict__ edst,
                                            int E, int half, int nbF) {
    if (blockIdx.x >= (unsigned)nbF) {
        __shared__ float s[32][33];
        int tx  = threadIdx.x & 31;
        int ty0 = threadIdx.x >> 5;          // 0..3
        int i0  = (blockIdx.x - nbF) * 32;
        #pragma unroll
        for (int r = 0; r < 8; r++) {
            int ty = ty0 + (r << 2);
            s[ty][tx] = x[ty * NV + i0 + tx];            // batch-major read
        }
        __syncthreads();
        #pragma unroll
        for (int r = 0; r < 8; r++) {
            int ty = ty0 + (r << 2);
            float xv = s[tx][ty];
            float fx = tanhf(xv);
            int o = (i0 + ty) * NB + tx;                 // node-major write
            g_xt[o]    = xv;
            g_fxt[o]   = fx;
            g_fxt16[o] = __float2half_rn(fx);
        }
        return;
    }
    // ---- buildF: two 4-edge segments per thread = 8 atomic chains ----
    int t  = blockIdx.x * 128 + threadIdx.x;
    int a0 = t << 2;            // segment A: [0, half)
    int b0 = half + a0;         // segment B: [half, E)  (half is 16B-aligned)
    bool fa = (a0 + 4 <= half);
    bool fb = (b0 + 4 <= E);
    if (fa && fb) {
        int4   sa = *(const int4*)  (esrc + a0);
        int4   da = *(const int4*)  (edst + a0);
        float4 wa = *(const float4*)(w    + a0);
        int4   sb = *(const int4*)  (esrc + b0);
        int4   db = *(const int4*)  (edst + b0);
        float4 wb = *(const float4*)(w    + b0);
        int p0 = atomicAdd(&g_cnt_dst[da.x << 5], 1);
        int p1 = atomicAdd(&g_cnt_dst[da.y << 5], 1);
        int p2 = atomicAdd(&g_cnt_dst[da.z << 5], 1);
        int p3 = atomicAdd(&g_cnt_dst[da.w << 5], 1);
        int p4 = atomicAdd(&g_cnt_dst[db.x << 5], 1);
        int p5 = atomicAdd(&g_cnt_dst[db.y << 5], 1);
        int p6 = atomicAdd(&g_cnt_dst[db.z << 5], 1);
        int p7 = atomicAdd(&g_cnt_dst[db.w << 5], 1);
        if (p0 < CAP) g_ellF[(da.x << 8) + p0] = make_float2(__int_as_float(sa.x << 5), wa.x);
        if (p1 < CAP) g_ellF[(da.y << 8) + p1] = make_float2(__int_as_float(sa.y << 5), wa.y);
        if (p2 < CAP) g_ellF[(da.z << 8) + p2] = make_float2(__int_as_float(sa.z << 5), wa.z);
        if (p3 < CAP) g_ellF[(da.w << 8) + p3] = make_float2(__int_as_float(sa.w << 5), wa.w);
        if (p4 < CAP) g_ellF[(db.x << 8) + p4] = make_float2(__int_as_float(sb.x << 5), wb.x);
        if (p5 < CAP) g_ellF[(db.y << 8) + p5] = make_float2(__int_as_float(sb.y << 5), wb.y);
        if (p6 < CAP) g_ellF[(db.z << 8) + p6] = make_float2(__int_as_float(sb.z << 5), wb.z);
        if (p7 < CAP) g_ellF[(db.w << 8) + p7] = make_float2(__int_as_float(sb.w << 5), wb.w);
    } else {
        for (int e = a0; e < half && e < a0 + 4; e++) insF(esrc[e], edst[e], w[e]);
        for (int e = b0; e < E && e < b0 + 4; e++)    insF(esrc[e], edst[e], w[e]);
    }
}

// SpMM inner loop over smem-staged row [jb,je): LDS.64 broadcast of
// (colOff, w), fp16 1-sector gathers via pre-offset lane pointer,
// unroll-8 for 8 gathers in flight. (R10-proven structure.)
__device__ __forceinline__ float spmm_smem(const float2* row,
                                           const __half* __restrict__ tabl,
                                           int jb, int je) {
    float a0 = 0.f, a1 = 0.f, a2 = 0.f, a3 = 0.f;
    int j = jb;
    for (; j + 8 <= je; j += 8) {
        float2 e0 = row[j + 0]; float2 e1 = row[j + 1];
        float2 e2 = row[j + 2]; float2 e3 = row[j + 3];
        float2 e4 = row[j + 4]; float2 e5 = row[j + 5];
        float2 e6 = row[j + 6]; float2 e7 = row[j + 7];
        float v0 = __half2float(tabl[__float_as_int(e0.x)]);
        float v1 = __half2float(tabl[__float_as_int(e1.x)]);
        float v2 = __half2float(tabl[__float_as_int(e2.x)]);
        float v3 = __half2float(tabl[__float_as_int(e3.x)]);
        float v4 = __half2float(tabl[__float_as_int(e4.x)]);
        float v5 = __half2float(tabl[__float_as_int(e5.x)]);
        float v6 = __half2float(tabl[__float_as_int(e6.x)]);
        float v7 = __half2float(tabl[__float_as_int(e7.x)]);
        a0 = fmaf(e0.y, v0, a0); a1 = fmaf(e1.y, v1, a1);
        a2 = fmaf(e2.y, v2, a2); a3 = fmaf(e3.y, v3, a3);
        a0 = fmaf(e4.y, v4, a0); a1 = fmaf(e5.y, v5, a1);
        a2 = fmaf(e6.y, v6, a2); a3 = fmaf(e7.y, v7, a3);
    }
    for (; j < je; j++) {
        float2 e0 = row[j];
        a0 = fmaf(e0.y, __half2float(tabl[__float_as_int(e0.x)]), a0);
    }
    return (a0 + a1) + (a2 + a3);
}

// ============================================================================
// k_mu with buildB riding along (R14-proven overlap): blocks [0, nbB) build
// the src-keyed ELL (consumed only by k_dx); blocks [nbB, ...) do the
// forward SpMM.
// ============================================================================
__global__ void __launch_bounds__(256, 8) k_mu(float* __restrict__ out,
                                               const float* __restrict__ w,
                                               const int*   __restrict__ esrc,
                                               const int*   __restrict__ edst,
                                               int E, int nbB) {
    if (blockIdx.x < (unsigned)nbB) {
        // ---- buildB: rows keyed by src ----
        int t  = blockIdx.x * 256 + threadIdx.x;
        int e0 = t << 2;
        if (e0 >= E) return;
        if (e0 + 4 <= E) {
            int4   s4 = *(const int4*)  (esrc + e0);
            int4   d4 = *(const int4*)  (edst + e0);
            float4 w4 = *(const float4*)(w    + e0);
            int q0 = atomicAdd(&g_cnt_src[s4.x << 5], 1);
            int q1 = atomicAdd(&g_cnt_src[s4.y << 5], 1);
            int q2 = atomicAdd(&g_cnt_src[s4.z << 5], 1);
            int q3 = atomicAdd(&g_cnt_src[s4.w << 5], 1);
            if (q0 < CAP) g_ellB[(s4.x << 8) + q0] = make_float2(__int_as_float(d4.x << 5), w4.x);
            if (q1 < CAP) g_ellB[(s4.y << 8) + q1] = make_float2(__int_as_float(d4.y << 5), w4.y);
            if (q2 < CAP) g_ellB[(s4.z << 8) + q2] = make_float2(__int_as_float(d4.z << 5), w4.z);
            if (q3 < CAP) g_ellB[(s4.w << 8) + q3] = make_float2(__int_as_float(d4.w << 5), w4.w);
        } else {
            for (int e = e0; e < E; e++) {
                int s = esrc[e], d = edst[e];
                int q = atomicAdd(&g_cnt_src[s << 5], 1);
                if (q < CAP) g_ellB[(s << 8) + q] = make_float2(__int_as_float(d << 5), w[e]);
            }
        }
        return;
    }
    // ---- forward SpMM: mu = sum w * fx[src]; eps = x - mu ----
    __shared__ float2 srow[2][CAP];
    __shared__ float  part[2][4][32];
    int warp  = threadIdx.x >> 5;
    int lane  = threadIdx.x & 31;
    int local = warp >> 2;
    int q     = warp & 3;
    int node0 = (blockIdx.x - nbB) << 1;

    int n0 = min(g_cnt_dst[node0 << 5],       CAP);
    int n1 = min(g_cnt_dst[(node0 + 1) << 5], CAP);
    for (int i = threadIdx.x; i < n0; i += 256) srow[0][i] = g_ellF[(node0 << 8) + i];
    for (int i = threadIdx.x; i < n1; i += 256) srow[1][i] = g_ellF[((node0 + 1) << 8) + i];
    __syncthreads();

    int n  = local ? n1 : n0;
    int jb = (n * q) >> 2;
    int je = (n * (q + 1)) >> 2;
    const __half* tabl = g_fxt16 + lane;

    part[local][q][lane] = spmm_smem(srow[local], tabl, jb, je);
    __syncthreads();

    if (q == 0) {
        float mu = (part[local][0][lane] + part[local][1][lane])
                 + (part[local][2][lane] + part[local][3][lane]);
        int node = node0 + local;
        int o = (node << 5) + lane;
        float eps = g_xt[o] - mu;
        g_epst[o]   = eps;
        g_epst16[o] = __float2half_rn(eps);
        out[lane * NV + node] = mu;                     // batch-major, scattered
        if (lane == 0) g_cnt_dst[node << 5] = 0;        // restore invariant
    }
}

// Backward SpMM: dx = -eps + (1-fx^2) * sum w * eps[dst];
// dx written straight to out[1] batch-major.
__global__ void __launch_bounds__(256, 8) k_dx(float* __restrict__ out) {
    __shared__ float2 srow[2][CAP];
    __shared__ float  part[2][4][32];
    int warp  = threadIdx.x >> 5;
    int lane  = threadIdx.x & 31;
    int local = warp >> 2;
    int q     = warp & 3;
    int node0 = blockIdx.x << 1;

    int n0 = min(g_cnt_src[node0 << 5],       CAP);
    int n1 = min(g_cnt_src[(node0 + 1) << 5], CAP);
    for (int i = threadIdx.x; i < n0; i += 256) srow[0][i] = g_ellB[(node0 << 8) + i];
    for (int i = threadIdx.x; i < n1; i += 256) srow[1][i] = g_ellB[((node0 + 1) << 8) + i];
    __syncthreads();

    int n  = local ? n1 : n0;
    int jb = (n * q) >> 2;
    int je = (n * (q + 1)) >> 2;
    const __half* tabl = g_epst16 + lane;

    part[local][q][lane] = spmm_smem(srow[local], tabl, jb, je);
    __syncthreads();

    if (q == 0) {
        float acc = (part[local][0][lane] + part[local][1][lane])
                  + (part[local][2][lane] + part[local][3][lane]);
        int node = node0 + local;
        int o = (node << 5) + lane;
        float eps = g_epst[o];
        float fx  = g_fxt[o];
        out[BN + lane * NV + node] = fmaf(fmaf(-fx, fx, 1.0f), acc, -eps);
        if (lane == 0) g_cnt_src[node << 5] = 0;        // restore invariant
    }
}

extern "C" void kernel_launch(void* const* d_in, const int* in_sizes, int n_in,
                              void* d_out, int out_size) {
    const float* x    = (const float*)d_in[0];
    const float* w    = (const float*)d_in[1];
    const int*   esrc = (const int*)d_in[2];
    const int*   edst = (const int*)d_in[3];
    float*       out  = (float*)d_out;
    int E    = in_sizes[1];
    int half = (((E + 1) / 2) + 3) & ~3;          // 16B-aligned split point
    if (half > E) half = E;
    int nbF  = ((half + 3) / 4 + 127) / 128;      // 128-thr build blocks (covers both halves)
    int nbB  = ((E + 3) / 4 + 255) / 256;         // 256-thr buildB blocks inside k_mu

    k_pf<<<nbF + 128, 128>>>(x, w, esrc, edst, E, half, nbF);
    k_mu<<<nbB + NV / 2, 256>>>(out, w, esrc, edst, E, nbB);
    k_dx<<<NV / 2, 256>>>(out);
}